// round 4
// baseline (speedup 1.0000x reference)
#include <cuda_runtime.h>

// RNNModel: 2-layer tanh RNN, B=2048, T=512, I=5, H=64, O=1.
// R4: weights in REGISTERS (zero W crossbar traffic), warp-specialized roles:
//   w0/w3: layer1 (rows split), W_hh0 in regs, x-proj via __ldg
//   w1:    h1 @ W_ih1 partials (all rows), W_ih1 in regs
//   w2:    b1 + h2 @ W_hh1 partials (all rows), W_hh1 in regs
//   w1/w2 exchange partials via smem, then each combines half the rows.
// h2 lags h1 by one step (h1 double-buffered) -> per-period = max(warp work).
// Grid: 147 CTAs x 128 thr, 14 rows/CTA (last CTA 4 rows). 513 periods.

#define TT  512
#define RPC 14
#define NCTA 147

// smem float offsets
#define OFF_H1 0         // h1[2][14][64] = 1792
#define OFF_H2 1792      // h2[14][64]    = 896
#define OFF_P1 2688      // part1: [14][32] ulonglong2 = 1792 floats
#define OFF_P2 4480      // part2: same
#define SMEM_FLOATS 6272
#define SMEM_BYTES (SMEM_FLOATS*4)

typedef unsigned long long ull;

__device__ __forceinline__ void fma2(ull &a, ull b, ull c){
    asm("fma.rn.f32x2 %0, %1, %2, %0;" : "+l"(a) : "l"(b), "l"(c));
}
__device__ __forceinline__ ull add2(ull a, ull b){
    ull r; asm("add.rn.f32x2 %0, %1, %2;" : "=l"(r) : "l"(a), "l"(b)); return r;
}
__device__ __forceinline__ ull pack2(float lo, float hi){
    ull r; asm("mov.b64 %0, {%1, %2};" : "=l"(r) : "f"(lo), "f"(hi)); return r;
}
__device__ __forceinline__ void unpk(ull a, float &lo, float &hi){
    asm("mov.b64 {%0, %1}, %2;" : "=f"(lo), "=f"(hi) : "l"(a));
}
__device__ __forceinline__ float fast_tanh(float x){
    float e;
    asm("ex2.approx.f32 %0, %1;" : "=f"(e) : "f"(x * 2.8853900817779268f));
    float r;
    asm("rcp.approx.f32 %0, %1;" : "=f"(r) : "f"(e + 1.0f));
    return fmaf(-2.0f, r, 1.0f);
}

__global__ void __launch_bounds__(128, 1) rnn_regw_kernel(
    const float* __restrict__ x,
    const float* __restrict__ W_ih0, const float* __restrict__ W_hh0,
    const float* __restrict__ b_ih0, const float* __restrict__ b_hh0,
    const float* __restrict__ W_ih1, const float* __restrict__ W_hh1,
    const float* __restrict__ b_ih1, const float* __restrict__ b_hh1,
    const float* __restrict__ fc_W,  const float* __restrict__ fc_b,
    float* __restrict__ out)
{
    extern __shared__ float sm[];
    const int tid = threadIdx.x;
    const int w   = tid >> 5;
    const int ln  = tid & 31;

    const int r0  = blockIdx.x * RPC;
    const int nr  = min(RPC, 2048 - r0);
    const int nr2 = nr >> 1;

    // zero h1 (both buffers) and h2
    for (int i = tid; i < OFF_P1; i += 128) sm[i] = 0.0f;

    // ---- role's weight matrix into registers: Wa = W[ln][k-pairs], Wb = W[ln+32][k-pairs]
    const float* Wsrc = (w == 1) ? W_ih1 : (w == 2) ? W_hh1 : W_hh0;
    ull Wa[32], Wb[32];
    {
        const ull* Wp = (const ull*)Wsrc;   // 32 ull per j-row
        #pragma unroll
        for (int q = 0; q < 32; q++){
            Wa[q] = Wp[ln*32 + q];
            Wb[q] = Wp[(ln+32)*32 + q];
        }
    }
    // light-warp constants
    float wa[5], wb[5];
    #pragma unroll
    for (int i = 0; i < 5; i++){
        wa[i] = W_ih0[ln*5 + i];
        wb[i] = W_ih0[(ln+32)*5 + i];
    }
    const float b0a = b_ih0[ln]    + b_hh0[ln];
    const float b0b = b_ih0[ln+32] + b_hh0[ln+32];
    const float b1a = b_ih1[ln]    + b_hh1[ln];
    const float b1b = b_ih1[ln+32] + b_hh1[ln+32];

    __syncthreads();

    float* h2 = sm + OFF_H2;
    ulonglong2* P1 = (ulonglong2*)(sm + OFF_P1);
    ulonglong2* P2 = (ulonglong2*)(sm + OFF_P2);

    for (int t = 0; t <= TT; t++){
        if (w == 0 || w == 3){
            // ---------- layer 1: produce h1[t] from h1[t-1] ----------
            if (t < TT){
                const float* h1src = sm + OFF_H1 + ((t+1)&1)*896;  // (t-1)&1
                float*       h1dst = sm + OFF_H1 + (t&1)*896;
                const int rlo = (w == 0) ? 0   : nr2;
                const int rhi = (w == 0) ? nr2 : nr;
                for (int r = rlo; r < rhi; r++){
                    float sa = b0a, sb = b0b;
                    const float* xr = x + (size_t)(r0 + r) * (TT*5) + t*5;
                    #pragma unroll
                    for (int i = 0; i < 5; i++){
                        float xv = __ldg(xr + i);
                        sa = fmaf(xv, wa[i], sa);
                        sb = fmaf(xv, wb[i], sb);
                    }
                    ull aA = pack2(sa, 0.f), aB = pack2(sb, 0.f);
                    const ulonglong2* hp = (const ulonglong2*)(h1src + r*64);
                    #pragma unroll
                    for (int q = 0; q < 16; q++){
                        ulonglong2 h4 = hp[q];
                        fma2(aA, Wa[2*q],   h4.x); fma2(aB, Wb[2*q],   h4.x);
                        fma2(aA, Wa[2*q+1], h4.y); fma2(aB, Wb[2*q+1], h4.y);
                    }
                    float lo, hi;
                    unpk(aA, lo, hi); float u = fast_tanh(lo + hi);
                    unpk(aB, lo, hi); float v = fast_tanh(lo + hi);
                    h1dst[r*64 + ln]      = u;
                    h1dst[r*64 + ln + 32] = v;
                }
            }
        } else {
            // ---------- layer 2: produce h2[t-1] from h1[t-1], h2[t-2] ----------
            if (t >= 1){
                if (w == 1){
                    const float* h1src = sm + OFF_H1 + ((t+1)&1)*896;  // h1[t-1]
                    for (int r = 0; r < nr; r++){
                        ull aA = 0, aB = 0;  // bias lives in partial2
                        const ulonglong2* hp = (const ulonglong2*)(h1src + r*64);
                        #pragma unroll
                        for (int q = 0; q < 16; q++){
                            ulonglong2 h4 = hp[q];
                            fma2(aA, Wa[2*q],   h4.x); fma2(aB, Wb[2*q],   h4.x);
                            fma2(aA, Wa[2*q+1], h4.y); fma2(aB, Wb[2*q+1], h4.y);
                        }
                        P1[r*32 + ln] = make_ulonglong2(aA, aB);
                    }
                } else {
                    for (int r = 0; r < nr; r++){
                        ull aA = pack2(b1a, 0.f), aB = pack2(b1b, 0.f);
                        const ulonglong2* hp = (const ulonglong2*)(h2 + r*64);
                        #pragma unroll
                        for (int q = 0; q < 16; q++){
                            ulonglong2 h4 = hp[q];
                            fma2(aA, Wa[2*q],   h4.x); fma2(aB, Wb[2*q],   h4.x);
                            fma2(aA, Wa[2*q+1], h4.y); fma2(aB, Wb[2*q+1], h4.y);
                        }
                        P2[r*32 + ln] = make_ulonglong2(aA, aB);
                    }
                }
                asm volatile("bar.sync 1, 64;" ::: "memory");  // w1+w2 only
                const int clo = (w == 1) ? 0   : nr2;
                const int chi = (w == 1) ? nr2 : nr;
                for (int r = clo; r < chi; r++){
                    ulonglong2 p1 = P1[r*32 + ln];
                    ulonglong2 p2 = P2[r*32 + ln];
                    ull aA = add2(p1.x, p2.x);
                    ull aB = add2(p1.y, p2.y);
                    float lo, hi;
                    unpk(aA, lo, hi); float u = fast_tanh(lo + hi);
                    unpk(aB, lo, hi); float v = fast_tanh(lo + hi);
                    h2[r*64 + ln]      = u;
                    h2[r*64 + ln + 32] = v;
                }
            }
        }
        __syncthreads();
    }

    // ---------- fc: out[r] = h2[r] . fc_W + fc_b (warp 0) ----------
    if (w == 0){
        const float fa = fc_W[ln], fb = fc_W[ln+32];
        const float fbias = fc_b[0];
        for (int r = 0; r < nr; r++){
            float p = h2[r*64 + ln]*fa + h2[r*64 + ln + 32]*fb;
            #pragma unroll
            for (int o = 16; o; o >>= 1)
                p += __shfl_xor_sync(0xffffffffu, p, o);
            if (ln == 0) out[r0 + r] = p + fbias;
        }
    }
}

extern "C" void kernel_launch(void* const* d_in, const int* in_sizes, int n_in,
                              void* d_out, int out_size)
{
    const float* x     = (const float*)d_in[0];
    const float* W_ih0 = (const float*)d_in[1];
    const float* W_hh0 = (const float*)d_in[2];
    const float* b_ih0 = (const float*)d_in[3];
    const float* b_hh0 = (const float*)d_in[4];
    const float* W_ih1 = (const float*)d_in[5];
    const float* W_hh1 = (const float*)d_in[6];
    const float* b_ih1 = (const float*)d_in[7];
    const float* b_hh1 = (const float*)d_in[8];
    const float* fc_W  = (const float*)d_in[9];
    const float* fc_b  = (const float*)d_in[10];
    float* out = (float*)d_out;

    rnn_regw_kernel<<<NCTA, 128, SMEM_BYTES>>>(
        x, W_ih0, W_hh0, b_ih0, b_hh0, W_ih1, W_hh1, b_ih1, b_hh1, fc_W, fc_b, out);
}

// round 6
// speedup vs baseline: 1.3830x; 1.3830x over previous
#include <cuda_runtime.h>

// RNNModel: 2-layer tanh RNN, B=2048, T=512, I=5, H=64, O=1.
// R6 (= R5 + compile fix): R3 uniform-warp structure + W_hh0 in REGISTERS per
// lane (128 regs), removing layer-1's W crossbar traffic. Layer 2 de-fused into
// two smem passes (W_hh1 first — depends only on stable h2_old, no barrier;
// then W_ih1 on h1_new). Grid: 128 CTAs x 128 thr, 4 warps x 4 rows.

#define BB 2048
#define TT 512
#define II_ 5

// shared float offsets
#define OFF_W1I  0        // W_ih1 [k2][ln] float4 = (W[l][2k2],W[l][2k2+1],W[l+32][2k2],W[l+32][2k2+1])
#define OFF_W1H  4096     // W_hh1 same packing
#define OFF_X    8192     // per-warp x stage: 4 warps * 512 ([r][tc][8])
#define OFF_H    10240    // per-warp hidden: 4 warps * 512 (h1[4][64], h2[4][64])
#define SMEM_FLOATS (10240 + 2048)
#define SMEM_BYTES (SMEM_FLOATS*4)

typedef unsigned long long ull;

__device__ __forceinline__ void fma2(ull &a, ull b, ull c){
    asm("fma.rn.f32x2 %0, %1, %2, %0;" : "+l"(a) : "l"(b), "l"(c));
}
__device__ __forceinline__ ull pack2(float lo, float hi){
    ull r; asm("mov.b64 %0, {%1, %2};" : "=l"(r) : "f"(lo), "f"(hi)); return r;
}
__device__ __forceinline__ void unpk(ull a, float &lo, float &hi){
    asm("mov.b64 {%0, %1}, %2;" : "=f"(lo), "=f"(hi) : "l"(a));
}
__device__ __forceinline__ float fast_tanh(float x){
    float e;
    asm("ex2.approx.f32 %0, %1;" : "=f"(e) : "f"(x * 2.8853900817779268f));
    float r;
    asm("rcp.approx.f32 %0, %1;" : "=f"(r) : "f"(e + 1.0f));
    return fmaf(-2.0f, r, 1.0f);
}

// x chunk staging: 16 steps * 4 rows * 5 floats = 320 elements, 10 per lane.
__device__ __forceinline__ void ld_chunk(const float* __restrict__ x, float* xg,
                                         int r0, int ln, int c){
    #pragma unroll
    for (int s = 0; s < 10; s++){
        int e = ln + 32*s;
        int r = e / 80, rem = e % 80;
        xg[s] = x[(size_t)(r0 + r) * (TT*II_) + (size_t)c * 80 + rem];
    }
}
__device__ __forceinline__ void st_chunk(float* xw, const float* xg, int ln){
    #pragma unroll
    for (int s = 0; s < 10; s++){
        int e = ln + 32*s;
        int r = e / 80, rem = e % 80;
        int tc = rem / 5, i = rem - tc*5;
        xw[r*128 + tc*8 + i] = xg[s];
    }
}

__global__ void __launch_bounds__(128, 1) rnn_r6_kernel(
    const float* __restrict__ x,
    const float* __restrict__ W_ih0, const float* __restrict__ W_hh0,
    const float* __restrict__ b_ih0, const float* __restrict__ b_hh0,
    const float* __restrict__ W_ih1, const float* __restrict__ W_hh1,
    const float* __restrict__ b_ih1, const float* __restrict__ b_hh1,
    const float* __restrict__ fc_W,  const float* __restrict__ fc_b,
    float* __restrict__ out)
{
    extern __shared__ float sm[];
    const int tid  = threadIdx.x;
    const int warp = tid >> 5;
    const int ln   = tid & 31;

    // ---- pack layer-2 weights into smem ----
    for (int idx = tid; idx < 1024; idx += 128){
        int k2 = idx >> 5, l = idx & 31, k = k2 * 2;
        ((float4*)(sm + OFF_W1I))[idx] = make_float4(W_ih1[l*64+k], W_ih1[l*64+k+1], W_ih1[(l+32)*64+k], W_ih1[(l+32)*64+k+1]);
        ((float4*)(sm + OFF_W1H))[idx] = make_float4(W_hh1[l*64+k], W_hh1[l*64+k+1], W_hh1[(l+32)*64+k], W_hh1[(l+32)*64+k+1]);
    }
    for (int idx = tid; idx < 4*512; idx += 128) sm[OFF_H + idx] = 0.0f;

    // ---- W_hh0 into registers: lane ln owns j=ln and j=ln+32, k packed in ull pairs ----
    ull R0a[32], R0b[32];
    {
        const ull* Wp = (const ull*)W_hh0;   // 32 ull per j-row
        #pragma unroll
        for (int q = 0; q < 32; q++){
            R0a[q] = Wp[ln*32 + q];
            R0b[q] = Wp[(ln+32)*32 + q];
        }
    }
    float wa[5], wb[5];
    #pragma unroll
    for (int i = 0; i < 5; i++){
        wa[i] = W_ih0[ln*5 + i];
        wb[i] = W_ih0[(ln+32)*5 + i];
    }
    const float b0a = b_ih0[ln]    + b_hh0[ln];
    const float b0b = b_ih0[ln+32] + b_hh0[ln+32];
    const float b1a = b_ih1[ln]    + b_hh1[ln];
    const float b1b = b_ih1[ln+32] + b_hh1[ln+32];

    __syncthreads();

    const int r0 = blockIdx.x * 16 + warp * 4;
    float* h1 = sm + OFF_H + warp * 512;   // h1[4][64]
    float* h2 = h1 + 256;                  // h2[4][64]
    float* xw = sm + OFF_X + warp * 512;   // x stage [4][16][8]

    const ulonglong2* W1Ip = (const ulonglong2*)(sm + OFF_W1I) + ln;
    const ulonglong2* W1Hp = (const ulonglong2*)(sm + OFF_W1H) + ln;

    // x chunk 0 -> smem; chunk 1 in flight
    float xg[10];
    ld_chunk(x, xg, r0, ln, 0);
    st_chunk(xw, xg, ln);
    __syncwarp();
    ld_chunk(x, xg, r0, ln, 1);

    float ta[4], tb[4];
    #pragma unroll
    for (int r = 0; r < 4; r++){ ta[r] = 0.f; tb[r] = 0.f; }

    for (int t = 0; t < TT; t++){
        const int tc = t & 15;
        if (tc == 0 && t){
            st_chunk(xw, xg, ln);
            __syncwarp();
            int c = (t >> 4) + 1;
            if (c < 32) ld_chunk(x, xg, r0, ln, c);
        }

        // ---- layer 1: bias + x-proj, then h1_old @ W_hh0^T from REGISTERS ----
        ull aA[4], aB[4];
        #pragma unroll
        for (int r = 0; r < 4; r++){
            const float* xr = xw + r*128 + tc*8;
            float4 xv = *(const float4*)xr;
            float x4  = xr[4];
            float sa = b0a, sb = b0b;
            sa = fmaf(xv.x, wa[0], sa); sb = fmaf(xv.x, wb[0], sb);
            sa = fmaf(xv.y, wa[1], sa); sb = fmaf(xv.y, wb[1], sb);
            sa = fmaf(xv.z, wa[2], sa); sb = fmaf(xv.z, wb[2], sb);
            sa = fmaf(xv.w, wa[3], sa); sb = fmaf(xv.w, wb[3], sb);
            sa = fmaf(x4,   wa[4], sa); sb = fmaf(x4,   wb[4], sb);
            aA[r] = pack2(sa, 0.f); aB[r] = pack2(sb, 0.f);
        }
        #pragma unroll
        for (int q = 0; q < 16; q++){
            ulonglong2 c0 = *(const ulonglong2*)(h1 +   0 + q*4);
            ulonglong2 c1 = *(const ulonglong2*)(h1 +  64 + q*4);
            ulonglong2 c2 = *(const ulonglong2*)(h1 + 128 + q*4);
            ulonglong2 c3 = *(const ulonglong2*)(h1 + 192 + q*4);
            fma2(aA[0],R0a[2*q],c0.x); fma2(aB[0],R0b[2*q],c0.x); fma2(aA[0],R0a[2*q+1],c0.y); fma2(aB[0],R0b[2*q+1],c0.y);
            fma2(aA[1],R0a[2*q],c1.x); fma2(aB[1],R0b[2*q],c1.x); fma2(aA[1],R0a[2*q+1],c1.y); fma2(aB[1],R0b[2*q+1],c1.y);
            fma2(aA[2],R0a[2*q],c2.x); fma2(aB[2],R0b[2*q],c2.x); fma2(aA[2],R0a[2*q+1],c2.y); fma2(aB[2],R0b[2*q+1],c2.y);
            fma2(aA[3],R0a[2*q],c3.x); fma2(aB[3],R0b[2*q],c3.x); fma2(aA[3],R0a[2*q+1],c3.y); fma2(aB[3],R0b[2*q+1],c3.y);
        }
        float u0[4], u1[4];
        #pragma unroll
        for (int r = 0; r < 4; r++){
            float lo, hi;
            unpk(aA[r], lo, hi); u0[r] = fast_tanh(lo + hi);
            unpk(aB[r], lo, hi); u1[r] = fast_tanh(lo + hi);
        }
        __syncwarp();                       // all lanes done reading h1_old
        #pragma unroll
        for (int r = 0; r < 4; r++){
            h1[r*64 + ln]      = u0[r];
            h1[r*64 + ln + 32] = u1[r];
        }

        // ---- layer 2, pass B first: h2_old @ W_hh1^T (stable, no barrier needed) ----
        #pragma unroll
        for (int r = 0; r < 4; r++){ aA[r] = pack2(b1a, 0.f); aB[r] = pack2(b1b, 0.f); }
        #pragma unroll
        for (int q = 0; q < 16; q++){
            ulonglong2 w0 = W1Hp[(2*q  )*32];
            ulonglong2 w1 = W1Hp[(2*q+1)*32];
            ulonglong2 g0 = *(const ulonglong2*)(h2 +   0 + q*4);
            ulonglong2 g1 = *(const ulonglong2*)(h2 +  64 + q*4);
            ulonglong2 g2 = *(const ulonglong2*)(h2 + 128 + q*4);
            ulonglong2 g3 = *(const ulonglong2*)(h2 + 192 + q*4);
            fma2(aA[0],w0.x,g0.x); fma2(aB[0],w0.y,g0.x); fma2(aA[0],w1.x,g0.y); fma2(aB[0],w1.y,g0.y);
            fma2(aA[1],w0.x,g1.x); fma2(aB[1],w0.y,g1.x); fma2(aA[1],w1.x,g1.y); fma2(aB[1],w1.y,g1.y);
            fma2(aA[2],w0.x,g2.x); fma2(aB[2],w0.y,g2.x); fma2(aA[2],w1.x,g2.y); fma2(aB[2],w1.y,g2.y);
            fma2(aA[3],w0.x,g3.x); fma2(aB[3],w0.y,g3.x); fma2(aA[3],w1.x,g3.y); fma2(aB[3],w1.y,g3.y);
        }
        __syncwarp();                       // h1_new visible (stores above drained)

        // ---- layer 2, pass A: h1_new @ W_ih1^T ----
        #pragma unroll
        for (int q = 0; q < 16; q++){
            ulonglong2 w0 = W1Ip[(2*q  )*32];
            ulonglong2 w1 = W1Ip[(2*q+1)*32];
            ulonglong2 e0 = *(const ulonglong2*)(h1 +   0 + q*4);
            ulonglong2 e1 = *(const ulonglong2*)(h1 +  64 + q*4);
            ulonglong2 e2 = *(const ulonglong2*)(h1 + 128 + q*4);
            ulonglong2 e3 = *(const ulonglong2*)(h1 + 192 + q*4);
            fma2(aA[0],w0.x,e0.x); fma2(aB[0],w0.y,e0.x); fma2(aA[0],w1.x,e0.y); fma2(aB[0],w1.y,e0.y);
            fma2(aA[1],w0.x,e1.x); fma2(aB[1],w0.y,e1.x); fma2(aA[1],w1.x,e1.y); fma2(aB[1],w1.y,e1.y);
            fma2(aA[2],w0.x,e2.x); fma2(aB[2],w0.y,e2.x); fma2(aA[2],w1.x,e2.y); fma2(aB[2],w1.y,e2.y);
            fma2(aA[3],w0.x,e3.x); fma2(aB[3],w0.y,e3.x); fma2(aA[3],w1.x,e3.y); fma2(aB[3],w1.y,e3.y);
        }
        #pragma unroll
        for (int r = 0; r < 4; r++){
            float lo, hi;
            unpk(aA[r], lo, hi); ta[r] = fast_tanh(lo + hi);
            unpk(aB[r], lo, hi); tb[r] = fast_tanh(lo + hi);
        }
        __syncwarp();                       // all lanes done reading h2_old (pass B finished)
        #pragma unroll
        for (int r = 0; r < 4; r++){
            h2[r*64 + ln]      = ta[r];
            h2[r*64 + ln + 32] = tb[r];
        }
        // h2_new visibility for next step's pass B is covered by the first
        // __syncwarp of the next iteration (after layer-1, before pass B reads h2).
    }

    // ---- fc ----
    const float fa = fc_W[ln], fb = fc_W[ln+32];
    #pragma unroll
    for (int r = 0; r < 4; r++){
        float p = ta[r]*fa + tb[r]*fb;
        #pragma unroll
        for (int o = 16; o; o >>= 1)
            p += __shfl_xor_sync(0xffffffffu, p, o);
        if (ln == 0) out[r0 + r] = p + fc_b[0];
    }
}

extern "C" void kernel_launch(void* const* d_in, const int* in_sizes, int n_in,
                              void* d_out, int out_size)
{
    const float* x     = (const float*)d_in[0];
    const float* W_ih0 = (const float*)d_in[1];
    const float* W_hh0 = (const float*)d_in[2];
    const float* b_ih0 = (const float*)d_in[3];
    const float* b_hh0 = (const float*)d_in[4];
    const float* W_ih1 = (const float*)d_in[5];
    const float* W_hh1 = (const float*)d_in[6];
    const float* b_ih1 = (const float*)d_in[7];
    const float* b_hh1 = (const float*)d_in[8];
    const float* fc_W  = (const float*)d_in[9];
    const float* fc_b  = (const float*)d_in[10];
    float* out = (float*)d_out;

    cudaFuncSetAttribute(rnn_r6_kernel,
                         cudaFuncAttributeMaxDynamicSharedMemorySize, SMEM_BYTES);

    rnn_r6_kernel<<<BB / 16, 128, SMEM_BYTES>>>(
        x, W_ih0, W_hh0, b_ih0, b_hh0, W_ih1, W_hh1, b_ih1, b_hh1, fc_W, fc_b, out);
}

// round 7
// speedup vs baseline: 1.7095x; 1.2361x over previous
#include <cuda_runtime.h>

// RNNModel: 2-layer tanh RNN, B=2048, T=512, I=5, H=64, O=1.
// R7: warp-pair software pipeline. CTA = 256 thr (8 warps), pair p = (warp p,
// warp p+4) owns 4 batch rows. Warp p: layer 1, W_hh0 in 128 REGS. Warp p+4:
// layer 2 (one step behind), W_hh1 in 128 REGS + W_ih1 from smem. h1 double-
// buffered in smem; ONE named bar.sync(64) per period. 2 warps/SMSP hide
// LDS latency; weight reg-arrays are branch-local so ptxas overlays them.
// Grid: 128 CTAs x 256 thr.

#define BB 2048
#define TT 512
#define II_ 5

// shared float offsets
#define OFF_W1I 0        // W_ih1 [k2][ln] float4 = (W[l][2k2],W[l][2k2+1],W[l+32][2k2],W[l+32][2k2+1])
#define OFF_H1  4096     // per pair 512: h1[2][4][64]
#define OFF_H2  6144     // per pair 256: h2[4][64]
#define OFF_X   7168     // per pair 512: x stage [4][16][8]
#define SMEM_FLOATS 9216
#define SMEM_BYTES (SMEM_FLOATS*4)

typedef unsigned long long ull;

__device__ __forceinline__ void fma2(ull &a, ull b, ull c){
    asm("fma.rn.f32x2 %0, %1, %2, %0;" : "+l"(a) : "l"(b), "l"(c));
}
__device__ __forceinline__ ull pack2(float lo, float hi){
    ull r; asm("mov.b64 %0, {%1, %2};" : "=l"(r) : "f"(lo), "f"(hi)); return r;
}
__device__ __forceinline__ void unpk(ull a, float &lo, float &hi){
    asm("mov.b64 {%0, %1}, %2;" : "=f"(lo), "=f"(hi) : "l"(a));
}
__device__ __forceinline__ float fast_tanh(float x){
    float e;
    asm("ex2.approx.f32 %0, %1;" : "=f"(e) : "f"(x * 2.8853900817779268f));
    float r;
    asm("rcp.approx.f32 %0, %1;" : "=f"(r) : "f"(e + 1.0f));
    return fmaf(-2.0f, r, 1.0f);
}
__device__ __forceinline__ void barp(int id){
    asm volatile("bar.sync %0, 64;" :: "r"(id) : "memory");
}

// x chunk staging: 16 steps * 4 rows * 5 floats = 320 elements, 10 per lane.
__device__ __forceinline__ void ld_chunk(const float* __restrict__ x, float* xg,
                                         int r0, int ln, int c){
    #pragma unroll
    for (int s = 0; s < 10; s++){
        int e = ln + 32*s;
        int r = e / 80, rem = e % 80;
        xg[s] = x[(size_t)(r0 + r) * (TT*II_) + (size_t)c * 80 + rem];
    }
}
__device__ __forceinline__ void st_chunk(float* xw, const float* xg, int ln){
    #pragma unroll
    for (int s = 0; s < 10; s++){
        int e = ln + 32*s;
        int r = e / 80, rem = e % 80;
        int tc = rem / 5, i = rem - tc*5;
        xw[r*128 + tc*8 + i] = xg[s];
    }
}

__global__ void __launch_bounds__(256, 1) rnn_pair_kernel(
    const float* __restrict__ x,
    const float* __restrict__ W_ih0, const float* __restrict__ W_hh0,
    const float* __restrict__ b_ih0, const float* __restrict__ b_hh0,
    const float* __restrict__ W_ih1, const float* __restrict__ W_hh1,
    const float* __restrict__ b_ih1, const float* __restrict__ b_hh1,
    const float* __restrict__ fc_W,  const float* __restrict__ fc_b,
    float* __restrict__ out)
{
    extern __shared__ float sm[];
    const int tid  = threadIdx.x;
    const int wid  = tid >> 5;
    const int ln   = tid & 31;
    const int pair = wid & 3;
    const int bid  = pair + 1;            // named barrier id (0 reserved)

    // ---- pack W_ih1 into smem; zero h1 bufs + h2 ----
    for (int idx = tid; idx < 1024; idx += 256){
        int k2 = idx >> 5, l = idx & 31, k = k2 * 2;
        ((float4*)(sm + OFF_W1I))[idx] =
            make_float4(W_ih1[l*64+k], W_ih1[l*64+k+1], W_ih1[(l+32)*64+k], W_ih1[(l+32)*64+k+1]);
    }
    for (int idx = tid; idx < 3072; idx += 256) sm[OFF_H1 + idx] = 0.0f;
    __syncthreads();

    const int r0  = blockIdx.x * 16 + pair * 4;
    float* h1b = sm + OFF_H1 + pair * 512;   // [2][4][64]
    float* h2  = sm + OFF_H2 + pair * 256;   // [4][64]
    float* xw  = sm + OFF_X  + pair * 512;   // [4][16][8]

    if (wid < 4){
        // ================= layer-1 role =================
        ull Ra[32], Rb[32];                   // W_hh0 rows ln, ln+32
        {
            const ull* Wp = (const ull*)W_hh0;
            #pragma unroll
            for (int q = 0; q < 32; q++){
                Ra[q] = __ldg(Wp + ln*32 + q);
                Rb[q] = __ldg(Wp + (ln+32)*32 + q);
            }
        }
        float wa[5], wb[5];
        #pragma unroll
        for (int i = 0; i < 5; i++){
            wa[i] = W_ih0[ln*5 + i];
            wb[i] = W_ih0[(ln+32)*5 + i];
        }
        const float b0a = b_ih0[ln]    + b_hh0[ln];
        const float b0b = b_ih0[ln+32] + b_hh0[ln+32];

        float xg[10];
        ld_chunk(x, xg, r0, ln, 0);
        st_chunk(xw, xg, ln);
        __syncwarp();
        ld_chunk(x, xg, r0, ln, 1);

        for (int t = 0; t < TT; t++){
            const int tc = t & 15;
            if (tc == 0 && t){
                st_chunk(xw, xg, ln);         // lanes synced by last period's bar
                __syncwarp();
                int c = (t >> 4) + 1;
                if (c < 32) ld_chunk(x, xg, r0, ln, c);
            }
            const float* hsrc = h1b + ((t+1)&1)*256;   // h1[t-1]
            float*       hdst = h1b + (t&1)*256;       // h1[t]

            ull aA[4], aB[4];
            #pragma unroll
            for (int r = 0; r < 4; r++){
                const float* xr = xw + r*128 + tc*8;
                float4 xv = *(const float4*)xr;
                float x4  = xr[4];
                float sa = b0a, sb = b0b;
                sa = fmaf(xv.x, wa[0], sa); sb = fmaf(xv.x, wb[0], sb);
                sa = fmaf(xv.y, wa[1], sa); sb = fmaf(xv.y, wb[1], sb);
                sa = fmaf(xv.z, wa[2], sa); sb = fmaf(xv.z, wb[2], sb);
                sa = fmaf(xv.w, wa[3], sa); sb = fmaf(xv.w, wb[3], sb);
                sa = fmaf(x4,   wa[4], sa); sb = fmaf(x4,   wb[4], sb);
                aA[r] = pack2(sa, 0.f); aB[r] = pack2(sb, 0.f);
            }
            #pragma unroll
            for (int q = 0; q < 16; q++){
                ulonglong2 c0 = *(const ulonglong2*)(hsrc +   0 + q*4);
                ulonglong2 c1 = *(const ulonglong2*)(hsrc +  64 + q*4);
                ulonglong2 c2 = *(const ulonglong2*)(hsrc + 128 + q*4);
                ulonglong2 c3 = *(const ulonglong2*)(hsrc + 192 + q*4);
                fma2(aA[0],Ra[2*q],c0.x); fma2(aB[0],Rb[2*q],c0.x); fma2(aA[0],Ra[2*q+1],c0.y); fma2(aB[0],Rb[2*q+1],c0.y);
                fma2(aA[1],Ra[2*q],c1.x); fma2(aB[1],Rb[2*q],c1.x); fma2(aA[1],Ra[2*q+1],c1.y); fma2(aB[1],Rb[2*q+1],c1.y);
                fma2(aA[2],Ra[2*q],c2.x); fma2(aB[2],Rb[2*q],c2.x); fma2(aA[2],Ra[2*q+1],c2.y); fma2(aB[2],Rb[2*q+1],c2.y);
                fma2(aA[3],Ra[2*q],c3.x); fma2(aB[3],Rb[2*q],c3.x); fma2(aA[3],Ra[2*q+1],c3.y); fma2(aB[3],Rb[2*q+1],c3.y);
            }
            #pragma unroll
            for (int r = 0; r < 4; r++){
                float lo, hi;
                unpk(aA[r], lo, hi); float u = fast_tanh(lo + hi);
                unpk(aB[r], lo, hi); float v = fast_tanh(lo + hi);
                hdst[r*64 + ln]      = u;
                hdst[r*64 + ln + 32] = v;
            }
            barp(bid);                        // end of period t
        }
        barp(bid);                            // cover layer-2's final period
    } else {
        // ================= layer-2 role =================
        ull Ra[32], Rb[32];                   // W_hh1 rows ln, ln+32
        {
            const ull* Wp = (const ull*)W_hh1;
            #pragma unroll
            for (int q = 0; q < 32; q++){
                Ra[q] = __ldg(Wp + ln*32 + q);
                Rb[q] = __ldg(Wp + (ln+32)*32 + q);
            }
        }
        const float b1a = b_ih1[ln]    + b_hh1[ln];
        const float b1b = b_ih1[ln+32] + b_hh1[ln+32];
        const ulonglong2* WIp = (const ulonglong2*)(sm + OFF_W1I) + ln;

        float ta[4], tb[4];
        #pragma unroll
        for (int r = 0; r < 4; r++){ ta[r] = 0.f; tb[r] = 0.f; }

        barp(bid);                            // wait for h1[0]
        for (int t = 1; t <= TT; t++){
            const float* hsrc = h1b + ((t+1)&1)*256;   // h1[t-1]

            ull aA[4], aB[4];
            #pragma unroll
            for (int r = 0; r < 4; r++){ aA[r] = pack2(b1a, 0.f); aB[r] = pack2(b1b, 0.f); }
            #pragma unroll
            for (int q = 0; q < 16; q++){
                ulonglong2 w0 = WIp[(2*q  )*32];
                ulonglong2 w1 = WIp[(2*q+1)*32];
                ulonglong2 e0 = *(const ulonglong2*)(hsrc +   0 + q*4);
                ulonglong2 e1 = *(const ulonglong2*)(hsrc +  64 + q*4);
                ulonglong2 e2 = *(const ulonglong2*)(hsrc + 128 + q*4);
                ulonglong2 e3 = *(const ulonglong2*)(hsrc + 192 + q*4);
                ulonglong2 g0 = *(const ulonglong2*)(h2 +   0 + q*4);
                ulonglong2 g1 = *(const ulonglong2*)(h2 +  64 + q*4);
                ulonglong2 g2 = *(const ulonglong2*)(h2 + 128 + q*4);
                ulonglong2 g3 = *(const ulonglong2*)(h2 + 192 + q*4);
                // W_ih1 (smem) * h1_new
                fma2(aA[0],w0.x,e0.x); fma2(aB[0],w0.y,e0.x); fma2(aA[0],w1.x,e0.y); fma2(aB[0],w1.y,e0.y);
                fma2(aA[1],w0.x,e1.x); fma2(aB[1],w0.y,e1.x); fma2(aA[1],w1.x,e1.y); fma2(aB[1],w1.y,e1.y);
                fma2(aA[2],w0.x,e2.x); fma2(aB[2],w0.y,e2.x); fma2(aA[2],w1.x,e2.y); fma2(aB[2],w1.y,e2.y);
                fma2(aA[3],w0.x,e3.x); fma2(aB[3],w0.y,e3.x); fma2(aA[3],w1.x,e3.y); fma2(aB[3],w1.y,e3.y);
                // W_hh1 (regs) * h2_old
                fma2(aA[0],Ra[2*q],g0.x); fma2(aB[0],Rb[2*q],g0.x); fma2(aA[0],Ra[2*q+1],g0.y); fma2(aB[0],Rb[2*q+1],g0.y);
                fma2(aA[1],Ra[2*q],g1.x); fma2(aB[1],Rb[2*q],g1.x); fma2(aA[1],Ra[2*q+1],g1.y); fma2(aB[1],Rb[2*q+1],g1.y);
                fma2(aA[2],Ra[2*q],g2.x); fma2(aB[2],Rb[2*q],g2.x); fma2(aA[2],Ra[2*q+1],g2.y); fma2(aB[2],Rb[2*q+1],g2.y);
                fma2(aA[3],Ra[2*q],g3.x); fma2(aB[3],Rb[2*q],g3.x); fma2(aA[3],Ra[2*q+1],g3.y); fma2(aB[3],Rb[2*q+1],g3.y);
            }
            #pragma unroll
            for (int r = 0; r < 4; r++){
                float lo, hi;
                unpk(aA[r], lo, hi); ta[r] = fast_tanh(lo + hi);
                unpk(aB[r], lo, hi); tb[r] = fast_tanh(lo + hi);
            }
            __syncwarp();                     // all lanes done reading h2_old
            #pragma unroll
            for (int r = 0; r < 4; r++){
                h2[r*64 + ln]      = ta[r];
                h2[r*64 + ln + 32] = tb[r];
            }
            barp(bid);                        // end of period t (also drains STS)
        }

        // ---- fc for this pair's 4 rows ----
        const float fa = fc_W[ln], fb = fc_W[ln+32];
        #pragma unroll
        for (int r = 0; r < 4; r++){
            float p = ta[r]*fa + tb[r]*fb;
            #pragma unroll
            for (int o = 16; o; o >>= 1)
                p += __shfl_xor_sync(0xffffffffu, p, o);
            if (ln == 0) out[r0 + r] = p + fc_b[0];
        }
    }
}

extern "C" void kernel_launch(void* const* d_in, const int* in_sizes, int n_in,
                              void* d_out, int out_size)
{
    const float* x     = (const float*)d_in[0];
    const float* W_ih0 = (const float*)d_in[1];
    const float* W_hh0 = (const float*)d_in[2];
    const float* b_ih0 = (const float*)d_in[3];
    const float* b_hh0 = (const float*)d_in[4];
    const float* W_ih1 = (const float*)d_in[5];
    const float* W_hh1 = (const float*)d_in[6];
    const float* b_ih1 = (const float*)d_in[7];
    const float* b_hh1 = (const float*)d_in[8];
    const float* fc_W  = (const float*)d_in[9];
    const float* fc_b  = (const float*)d_in[10];
    float* out = (float*)d_out;

    rnn_pair_kernel<<<BB / 16, 256, SMEM_BYTES>>>(
        x, W_ih0, W_hh0, b_ih0, b_hh0, W_ih1, W_hh1, b_ih1, b_hh1, fc_W, fc_b, out);
}